// round 17
// baseline (speedup 1.0000x reference)
#include <cuda_runtime.h>

// Problem constants
#define B_ROWS 64
#define N_COLS 262144
#define THREADS 256
#define V8_PER_THREAD 2                 // 2 x 256-bit loads = 16 elems per array
#define ELEMS_PER_BLOCK (THREADS * V8_PER_THREAD * 8)   // 4096 elems
#define BLOCKS_PER_ROW (N_COLS / ELEMS_PER_BLOCK)       // 64
#define TOTAL_BLOCKS (B_ROWS * BLOCKS_PER_ROW)          // 4096

// Per-block partial: (sum_t, sum t*log2(p), sum (1-t)*log2(1-p), pad).
// Overwritten unconditionally each launch -> no zeroing needed.
__device__ float4 g_part[TOTAL_BLOCKS];
__device__ unsigned int g_rowcnt[B_ROWS];   // zero-init; reset by row finalizer
__device__ double g_total;                  // zero-init; reset by last finalizer
__device__ unsigned int g_fin;              // zero-init; reset by last finalizer

// Blackwell 256-bit global load (LDG.E.256): 8 floats in one instruction.
__device__ __forceinline__ void ldg256(const float* addr, float* r) {
    asm volatile("ld.global.v8.f32 {%0,%1,%2,%3,%4,%5,%6,%7}, [%8];"
                 : "=f"(r[0]), "=f"(r[1]), "=f"(r[2]), "=f"(r[3]),
                   "=f"(r[4]), "=f"(r[5]), "=f"(r[6]), "=f"(r[7])
                 : "l"(addr));
}

__global__ __launch_bounds__(THREADS) void bce_onepass_kernel(
    const float* __restrict__ p, const float* __restrict__ t,
    float* __restrict__ out) {
    const int row = blockIdx.y;
    const int chunk = blockIdx.x;            // fastest-varying: row blocks contiguous
    const int tid = threadIdx.x;
    const int base = row * N_COLS + chunk * ELEMS_PER_BLOCK + tid * 8;

    // ---- mainloop: byte-identical to R16 (tied-best) ----
    float pv[V8_PER_THREAD][8], tv[V8_PER_THREAD][8];
#pragma unroll
    for (int v = 0; v < V8_PER_THREAD; v++) {
        ldg256(&p[base + v * THREADS * 8], pv[v]);
        ldg256(&t[base + v * THREADS * 8], tv[v]);
    }

    float st = 0.f, s1 = 0.f, sq = 0.f, sw = 0.f;
#pragma unroll
    for (int v = 0; v < V8_PER_THREAD; v++) {
#pragma unroll
        for (int e = 0; e < 8; e++) {
            float pe = pv[v][e];
            float te = tv[v][e];
            float lp = __log2f(pe);           // scaled by ln2 at row finalize
            float lq = __log2f(1.0f - pe);
            st += te;
            s1 = fmaf(te, lp, s1);
            sq += lq;
            sw = fmaf(te, lq, sw);
        }
    }
    float s2 = sq - sw;

#pragma unroll
    for (int o = 16; o > 0; o >>= 1) {
        st += __shfl_down_sync(0xFFFFFFFFu, st, o);
        s1 += __shfl_down_sync(0xFFFFFFFFu, s1, o);
        s2 += __shfl_down_sync(0xFFFFFFFFu, s2, o);
    }

    __shared__ float sh_st[THREADS / 32], sh_s1[THREADS / 32], sh_s2[THREADS / 32];
    const int warp = tid >> 5;
    const int lane = tid & 31;
    if (lane == 0) { sh_st[warp] = st; sh_s1[warp] = s1; sh_s2[warp] = s2; }
    __syncthreads();

    if (warp == 0) {
        const int nw = THREADS / 32;   // 8
        float a = (lane < nw) ? sh_st[lane] : 0.f;
        float b = (lane < nw) ? sh_s1[lane] : 0.f;
        float c = (lane < nw) ? sh_s2[lane] : 0.f;
#pragma unroll
        for (int o = 4; o > 0; o >>= 1) {
            a += __shfl_down_sync(0xFFFFFFFFu, a, o);
            b += __shfl_down_sync(0xFFFFFFFFu, b, o);
            c += __shfl_down_sync(0xFFFFFFFFu, c, o);
        }
        if (lane == 0) {
            g_part[row * BLOCKS_PER_ROW + chunk] = make_float4(a, b, c, 0.f);
            // Fire-and-forget PER-ROW arrival; .release orders the STG above.
            asm volatile("red.release.gpu.global.add.u32 [%0], 1;"
                         :: "l"(&g_rowcnt[row]) : "memory");
        }
    }

    // Non-finalizer blocks exit with zero waiting (proven-free tail).
    if (chunk != BLOCKS_PER_ROW - 1) return;
    if (warp != 0) return;             // row finalizer: warp 0 only (64 blocks)

    // ---- row finalize: wait only for THIS row's peers (co-scheduled) ----
    if (lane == 0) {
        unsigned int c;
        do {
            asm volatile("ld.acquire.gpu.global.u32 %0, [%1];"
                         : "=r"(c) : "l"(&g_rowcnt[row]) : "memory");
            if (c == BLOCKS_PER_ROW) break;
            __nanosleep(32);
        } while (1);
    }
    __syncwarp();

    // Read this row's 64 partials via L2 (bypass L1: writers stored via L2).
    float4 v0 = __ldcg(&g_part[row * BLOCKS_PER_ROW + lane]);
    float4 v1 = __ldcg(&g_part[row * BLOCKS_PER_ROW + lane + 32]);
    float a = v0.x + v1.x, b = v0.y + v1.y, c = v0.z + v1.z;
#pragma unroll
    for (int o = 16; o > 0; o >>= 1) {
        a += __shfl_down_sync(0xFFFFFFFFu, a, o);
        b += __shfl_down_sync(0xFFFFFFFFu, b, o);
        c += __shfl_down_sync(0xFFFFFFFFu, c, o);
    }

    if (lane == 0) {
        const double LN2 = 0.6931471805599453;
        double beta = 1.0 - (double)a / (double)N_COLS;
        double contrib = (beta * (double)b + (1.0 - beta) * (double)c) * LN2;

        g_rowcnt[row] = 0u;            // reset own row counter for next replay

        // Accumulate row contribution; ordering provided by the release half
        // of the acq_rel counter bump below (same thread, program order).
        asm volatile("red.gpu.global.add.f64 [%0], %1;"
                     :: "l"(&g_total), "d"(contrib) : "memory");

        unsigned int prev;
        asm volatile("atom.add.acq_rel.gpu.u32 %0, [%1], 1;"
                     : "=r"(prev) : "l"(&g_fin) : "memory");
        if (prev == B_ROWS - 1u) {
            // Last finalizer: acquire above makes all 64 REDGs visible.
            double tot;
            asm volatile("ld.global.cg.f64 %0, [%1];"
                         : "=d"(tot) : "l"(&g_total) : "memory");
            out[0] = (float)(-tot);
            g_total = 0.0;             // reset for next graph replay
            *((volatile unsigned int*)&g_fin) = 0u;
        }
    }
}

extern "C" void kernel_launch(void* const* d_in, const int* in_sizes, int n_in,
                              void* d_out, int out_size) {
    const float* p = (const float*)d_in[0];  // input (probabilities)
    const float* t = (const float*)d_in[1];  // target
    float* out = (float*)d_out;

    dim3 grid(BLOCKS_PER_ROW, B_ROWS);
    bce_onepass_kernel<<<grid, THREADS>>>(p, t, out);
}